// round 9
// baseline (speedup 1.0000x reference)
#include <cuda_runtime.h>
#include <cuda.h>
#include <math.h>
#include <stdint.h>

#define D    1280
#define H    20
#define HDIM 64

// Attention tiling (unchanged HMMA flash kernel)
#define AT_TQ 128
#define AT_TK 64
#define QS_STRIDE 68
#define KS_STRIDE 68
#define VS_STRIDE 72
#define PS_STRIDE 68
#define ATTN_SMEM_FLOATS (AT_TQ*QS_STRIDE + AT_TK*KS_STRIDE + AT_TK*VS_STRIDE + AT_TQ*PS_STRIDE)
#define ATTN_SMEM_BYTES (ATTN_SMEM_FLOATS * 4)

// GEMM tiling: 128M x 256N x 32K, 512 threads, 3-stage TMA pipeline
#define BM 128
#define BN 256
#define BK 32
#define STAGES 3
#define A_STAGE_BYTES 16384          // 128 x 32 floats
#define B_STAGE_BYTES 32768          // 256 x 32 floats
#define STAGE_BYTES   (A_STAGE_BYTES + B_STAGE_BYTES)   // 49152
#define SMEM_DATA0    1024
#define GEMM_SMEM_BYTES (SMEM_DATA0 + STAGES * STAGE_BYTES)   // 148480
#define TILE_TX STAGE_BYTES

// Scratch (allocation-free): fixed problem shapes.
__device__ float g_q[1600 * 1280];
__device__ float g_kv[6000 * 2560];
__device__ float g_attn[1600 * 1280];
__device__ float g_hid[1600 * 1280];
__device__ float g_cross[6000 * 1280];
__device__ float g_wq[1280 * 1280];    // transposed [N][K]
__device__ float g_wkv[2560 * 1280];   // transposed [N][K]
__device__ float g_wo[1280 * 1280];    // transposed [N][K]

// ---------------------------------------------------------------------------
// PTX helpers
// ---------------------------------------------------------------------------
__device__ __forceinline__ float to_tf32(float x) {
    uint32_t y;
    asm("cvt.rna.tf32.f32 %0, %1;" : "=r"(y) : "f"(x));
    return __uint_as_float(y);
}

__device__ __forceinline__ void mma_tf32(float* d, const uint32_t* a, const uint32_t* b) {
    asm volatile(
        "mma.sync.aligned.m16n8k8.row.col.f32.tf32.tf32.f32 "
        "{%0,%1,%2,%3}, {%4,%5,%6,%7}, {%8,%9}, {%0,%1,%2,%3};\n"
        : "+f"(d[0]), "+f"(d[1]), "+f"(d[2]), "+f"(d[3])
        : "r"(a[0]), "r"(a[1]), "r"(a[2]), "r"(a[3]), "r"(b[0]), "r"(b[1]));
}

__device__ __forceinline__ uint32_t smem_u32(const void* p) {
    return (uint32_t)__cvta_generic_to_shared(p);
}

#define MBARRIER_INIT(addr, count) \
    asm volatile("mbarrier.init.shared.b64 [%0], %1;" :: "r"((uint32_t)(addr)), "r"((uint32_t)(count)) : "memory")

#define MBARRIER_EXPECT_TX(addr, tx) \
    asm volatile("mbarrier.arrive.expect_tx.shared.b64 _, [%0], %1;" :: "r"((uint32_t)(addr)), "r"((uint32_t)(tx)) : "memory")

#define MBARRIER_WAIT_PARITY(mbar_smem_addr, phase_parity) do { \
    uint32_t _mbar = (uint32_t)(mbar_smem_addr); \
    uint32_t _parity = (uint32_t)(phase_parity); \
    uint32_t _done; \
    asm volatile( \
        "{\n\t.reg .pred p;\n\t" \
        "mbarrier.try_wait.parity.acquire.cta.shared::cta.b64 p, [%1], %2;\n\t" \
        "selp.b32 %0, 1, 0, p;\n\t}" \
        : "=r"(_done) : "r"(_mbar), "r"(_parity) : "memory"); \
    if (!_done) { \
        asm volatile( \
            "{\n\t.reg .pred P1;\n\t" \
            "WAIT_LOOP_%=:\n\t" \
            "mbarrier.try_wait.parity.acquire.cta.shared::cta.b64 P1, [%0], %1, 0x989680;\n\t" \
            "@P1 bra.uni WAIT_DONE_%=;\n\t" \
            "bra.uni WAIT_LOOP_%=;\n\t" \
            "WAIT_DONE_%=:\n\t}" \
            :: "r"(_mbar), "r"(_parity) : "memory"); \
    } \
} while(0)

#define TMA_LOAD_2D(smem_addr, map_ptr, cx, cy, mbar) \
    asm volatile( \
        "cp.async.bulk.tensor.2d.shared::cta.global.tile.mbarrier::complete_tx::bytes " \
        "[%0], [%1, {%2, %3}], [%4];" \
        :: "r"((uint32_t)(smem_addr)), "l"(map_ptr), "r"((int)(cx)), "r"((int)(cy)), \
           "r"((uint32_t)(mbar)) : "memory")

// ---------------------------------------------------------------------------
// Elementwise fp32 -> tf32(RN)
// ---------------------------------------------------------------------------
__global__ void cvt_tf32_kernel(const float* __restrict__ in,
                                float* __restrict__ out, int n4)
{
    int i = blockIdx.x * blockDim.x + threadIdx.x;
    if (i < n4) {
        float4 v = reinterpret_cast<const float4*>(in)[i];
        v.x = to_tf32(v.x); v.y = to_tf32(v.y);
        v.z = to_tf32(v.z); v.w = to_tf32(v.w);
        reinterpret_cast<float4*>(out)[i] = v;
    }
}

// ---------------------------------------------------------------------------
// Transpose + tf32 round: in[K][N] -> out[N][K]. K,N multiples of 32.
// ---------------------------------------------------------------------------
__global__ void transpose_cvt_kernel(const float* __restrict__ in,
                                     float* __restrict__ out, int K, int N)
{
    __shared__ float t[32][33];
    int k0 = blockIdx.y * 32, n0 = blockIdx.x * 32;
    int tx = threadIdx.x, ty = threadIdx.y;   // 32 x 8
    #pragma unroll
    for (int i = 0; i < 32; i += 8)
        t[ty + i][tx] = in[(size_t)(k0 + ty + i) * N + n0 + tx];
    __syncthreads();
    #pragma unroll
    for (int i = 0; i < 32; i += 8)
        out[(size_t)(n0 + ty + i) * K + k0 + tx] = to_tf32(t[tx][ty + i]);
}

// ---------------------------------------------------------------------------
// TMA + HMMA tf32 GEMM: C[M,N] = (A[M,K] @ Bt[N,K]^T + bias) * scale
// Tile 128x256x32, 512 threads = 16 warps (2M x 8N), warp tile 64x32.
// A/B staged via 2D TMA (SW128); fragment LDS uses the matching XOR swizzle.
// ---------------------------------------------------------------------------
__global__ __launch_bounds__(512, 1) void tc_gemm_kernel(
    const __grid_constant__ CUtensorMap tmA,
    const __grid_constant__ CUtensorMap tmB,
    const float* __restrict__ bias, float* __restrict__ C,
    int M, int N, int K, float scale, int round_out)
{
    extern __shared__ __align__(1024) char smem[];
    uint32_t sb = smem_u32(smem);

    int tid = threadIdx.x, wid = tid >> 5, lane = tid & 31;
    int wm = wid >> 3, wn = wid & 7;          // 2 x 8 warp grid
    int qr = lane >> 2, qc = lane & 3;
    int brow = blockIdx.y * BM;
    int bcol = blockIdx.x * BN;
    int ntiles = K / BK;
    int mBase = wm * 64, nBase = wn * 32;

    if (tid < STAGES) MBARRIER_INIT(sb + tid * 8, 1);
    __syncthreads();

    // Prefetch stages 0..STAGES-2
    if (tid == 0) {
        #pragma unroll
        for (int s = 0; s < STAGES - 1; s++) {
            MBARRIER_EXPECT_TX(sb + s * 8, TILE_TX);
            TMA_LOAD_2D(sb + SMEM_DATA0 + s * STAGE_BYTES, &tmA, s * BK, brow, sb + s * 8);
            TMA_LOAD_2D(sb + SMEM_DATA0 + s * STAGE_BYTES + A_STAGE_BYTES, &tmB,
                        s * BK, bcol, sb + s * 8);
        }
    }

    float acc[4][4][4];
    #pragma unroll
    for (int i = 0; i < 4; i++)
        #pragma unroll
        for (int j = 0; j < 4; j++)
            #pragma unroll
            for (int t = 0; t < 4; t++) acc[i][j][t] = 0.f;

    // Swizzled row byte offsets (TMA SW128: chunk ^= (row & 7), xor term = qr<<4)
    uint32_t xorv = (uint32_t)(qr << 4);
    uint32_t aOff[4], bOff[4];
    #pragma unroll
    for (int mi = 0; mi < 4; mi++) aOff[mi] = (uint32_t)(mBase + mi * 16 + qr) * 128u;
    #pragma unroll
    for (int nj = 0; nj < 4; nj++) bOff[nj] = (uint32_t)(nBase + nj * 8 + qr) * 128u;

    int ph[STAGES] = {0, 0, 0};

    for (int t = 0; t < ntiles; t++) {
        int buf = t % STAGES;
        // Issue stage t+STAGES-1 (its buffer was last consumed at t-1; synced below)
        if (t + STAGES - 1 < ntiles && tid == 0) {
            int nb = (t + STAGES - 1) % STAGES;
            MBARRIER_EXPECT_TX(sb + nb * 8, TILE_TX);
            TMA_LOAD_2D(sb + SMEM_DATA0 + nb * STAGE_BYTES, &tmA,
                        (t + STAGES - 1) * BK, brow, sb + nb * 8);
            TMA_LOAD_2D(sb + SMEM_DATA0 + nb * STAGE_BYTES + A_STAGE_BYTES, &tmB,
                        (t + STAGES - 1) * BK, bcol, sb + nb * 8);
        }

        MBARRIER_WAIT_PARITY(sb + buf * 8, ph[buf]);
        ph[buf] ^= 1;

        const char* Ab = smem + SMEM_DATA0 + buf * STAGE_BYTES;
        const char* Bb = Ab + A_STAGE_BYTES;

        #pragma unroll
        for (int ks = 0; ks < 32; ks += 8) {
            uint32_t c0 = ((uint32_t)((ks + qc) * 4)) ^ xorv;
            uint32_t c1 = ((uint32_t)((ks + qc + 4) * 4)) ^ xorv;
            uint32_t af[4][4], bf[4][2];
            #pragma unroll
            for (int mi = 0; mi < 4; mi++) {
                af[mi][0] = *(const uint32_t*)(Ab + aOff[mi] + c0);
                af[mi][1] = *(const uint32_t*)(Ab + aOff[mi] + 1024 + c0);
                af[mi][2] = *(const uint32_t*)(Ab + aOff[mi] + c1);
                af[mi][3] = *(const uint32_t*)(Ab + aOff[mi] + 1024 + c1);
            }
            #pragma unroll
            for (int nj = 0; nj < 4; nj++) {
                bf[nj][0] = *(const uint32_t*)(Bb + bOff[nj] + c0);
                bf[nj][1] = *(const uint32_t*)(Bb + bOff[nj] + c1);
            }
            #pragma unroll
            for (int mi = 0; mi < 4; mi++)
                #pragma unroll
                for (int nj = 0; nj < 4; nj++)
                    mma_tf32(acc[mi][nj], af[mi], bf[nj]);
        }
        __syncthreads();
    }

    // ---- epilogue ----
    #pragma unroll
    for (int mi = 0; mi < 4; mi++) {
        int row0 = brow + mBase + mi * 16 + qr;
        #pragma unroll
        for (int nj = 0; nj < 4; nj++) {
            int col0 = bcol + nBase + nj * 8 + qc * 2;
            float b0 = bias[col0], b1 = bias[col0 + 1];
            float v00 = (acc[mi][nj][0] + b0) * scale;
            float v01 = (acc[mi][nj][1] + b1) * scale;
            float v10 = (acc[mi][nj][2] + b0) * scale;
            float v11 = (acc[mi][nj][3] + b1) * scale;
            if (round_out) {
                v00 = to_tf32(v00); v01 = to_tf32(v01);
                v10 = to_tf32(v10); v11 = to_tf32(v11);
            }
            if (row0 < M) {
                C[(size_t)row0 * N + col0    ] = v00;
                C[(size_t)row0 * N + col0 + 1] = v01;
            }
            if (row0 + 8 < M) {
                C[(size_t)(row0 + 8) * N + col0    ] = v10;
                C[(size_t)(row0 + 8) * N + col0 + 1] = v11;
            }
        }
    }
}

// ---------------------------------------------------------------------------
// Tensor-core flash attention (HMMA tf32, unchanged). Inputs pre-rounded.
// ---------------------------------------------------------------------------
__global__ __launch_bounds__(256) void attn_mma_kernel(
    const float* __restrict__ q, const float* __restrict__ kv,
    const int* __restrict__ seq_lens, float* __restrict__ outbuf,
    int nB, int enc)
{
    extern __shared__ float sm[];
    float* Qs = sm;
    float* Ks = Qs + AT_TQ * QS_STRIDE;
    float* Vs = Ks + AT_TK * KS_STRIDE;
    float* Ps = Vs + AT_TK * VS_STRIDE;

    int h = blockIdx.x, b = blockIdx.y, tile = blockIdx.z;
    int qstart = 0;
    for (int i = 0; i < b; i++) qstart += seq_lens[i];
    int qlen = seq_lens[b];
    if (tile * AT_TQ >= qlen) return;
    int qrow0 = qstart + tile * AT_TQ;
    int rows = min(AT_TQ, qlen - tile * AT_TQ);
    size_t kvbase = (size_t)b * enc;

    int tid = threadIdx.x, wid = tid >> 5, lane = tid & 31;
    int qr = lane >> 2, qc = lane & 3;
    int mrow = wid * 16;

    for (int i = tid; i < AT_TQ * 16; i += 256) {
        int r = i >> 4, c4 = (i & 15) << 2;
        float4 v = make_float4(0.f, 0.f, 0.f, 0.f);
        if (r < rows)
            v = *reinterpret_cast<const float4*>(q + (size_t)(qrow0 + r) * D + h * HDIM + c4);
        *reinterpret_cast<float4*>(Qs + r * QS_STRIDE + c4) = v;
    }

    float O[8][4];
    #pragma unroll
    for (int nj = 0; nj < 8; nj++)
        #pragma unroll
        for (int t = 0; t < 4; t++) O[nj][t] = 0.f;
    float m0 = -1e30f, m1 = -1e30f, l0 = 0.f, l1 = 0.f;

    __syncthreads();

    for (int kc = 0; kc < enc; kc += AT_TK) {
        int kn = min(AT_TK, enc - kc);

        for (int i = tid; i < AT_TK * 16; i += 256) {
            int r = i >> 4, c4 = (i & 15) << 2;
            float4 kv4 = make_float4(0.f, 0.f, 0.f, 0.f);
            float4 vv4 = make_float4(0.f, 0.f, 0.f, 0.f);
            if (r < kn) {
                const float* rp = kv + (kvbase + kc + r) * (size_t)(2 * D) + h * HDIM;
                kv4 = *reinterpret_cast<const float4*>(rp + c4);
                vv4 = *reinterpret_cast<const float4*>(rp + D + c4);
            }
            *reinterpret_cast<float4*>(Ks + r * KS_STRIDE + c4) = kv4;
            *reinterpret_cast<float4*>(Vs + r * VS_STRIDE + c4) = vv4;
        }
        __syncthreads();

        float s[8][4];
        #pragma unroll
        for (int nj = 0; nj < 8; nj++)
            #pragma unroll
            for (int t = 0; t < 4; t++) s[nj][t] = 0.f;

        #pragma unroll
        for (int ks = 0; ks < AT_TK; ks += 8) {
            uint32_t a[4];
            a[0] = __float_as_uint(Qs[(mrow + qr    ) * QS_STRIDE + ks + qc    ]);
            a[1] = __float_as_uint(Qs[(mrow + qr + 8) * QS_STRIDE + ks + qc    ]);
            a[2] = __float_as_uint(Qs[(mrow + qr    ) * QS_STRIDE + ks + qc + 4]);
            a[3] = __float_as_uint(Qs[(mrow + qr + 8) * QS_STRIDE + ks + qc + 4]);
            #pragma unroll
            for (int nj = 0; nj < 8; nj++) {
                uint32_t bb[2];
                bb[0] = __float_as_uint(Ks[(nj * 8 + qr) * KS_STRIDE + ks + qc    ]);
                bb[1] = __float_as_uint(Ks[(nj * 8 + qr) * KS_STRIDE + ks + qc + 4]);
                mma_tf32(s[nj], a, bb);
            }
        }

        if (kn < AT_TK) {
            #pragma unroll
            for (int nj = 0; nj < 8; nj++) {
                int c0 = nj * 8 + 2 * qc;
                if (c0     >= kn) { s[nj][0] = -1e30f; s[nj][2] = -1e30f; }
                if (c0 + 1 >= kn) { s[nj][1] = -1e30f; s[nj][3] = -1e30f; }
            }
        }

        float mx0 = -1e30f, mx1 = -1e30f;
        #pragma unroll
        for (int nj = 0; nj < 8; nj++) {
            mx0 = fmaxf(mx0, fmaxf(s[nj][0], s[nj][1]));
            mx1 = fmaxf(mx1, fmaxf(s[nj][2], s[nj][3]));
        }
        mx0 = fmaxf(mx0, __shfl_xor_sync(0xffffffffu, mx0, 1));
        mx0 = fmaxf(mx0, __shfl_xor_sync(0xffffffffu, mx0, 2));
        mx1 = fmaxf(mx1, __shfl_xor_sync(0xffffffffu, mx1, 1));
        mx1 = fmaxf(mx1, __shfl_xor_sync(0xffffffffu, mx1, 2));

        float mn0 = fmaxf(m0, mx0), mn1 = fmaxf(m1, mx1);
        float al0 = __expf(m0 - mn0), al1 = __expf(m1 - mn1);
        m0 = mn0; m1 = mn1;

        float rs0 = 0.f, rs1 = 0.f;
        #pragma unroll
        for (int nj = 0; nj < 8; nj++) {
            float p0 = __expf(s[nj][0] - mn0);
            float p1 = __expf(s[nj][1] - mn0);
            float p2 = __expf(s[nj][2] - mn1);
            float p3 = __expf(s[nj][3] - mn1);
            rs0 += p0 + p1; rs1 += p2 + p3;
            int c = nj * 8 + 2 * qc;
            Ps[(mrow + qr    ) * PS_STRIDE + c    ] = to_tf32(p0);
            Ps[(mrow + qr    ) * PS_STRIDE + c + 1] = to_tf32(p1);
            Ps[(mrow + qr + 8) * PS_STRIDE + c    ] = to_tf32(p2);
            Ps[(mrow + qr + 8) * PS_STRIDE + c + 1] = to_tf32(p3);
            O[nj][0] *= al0; O[nj][1] *= al0;
            O[nj][2] *= al1; O[nj][3] *= al1;
        }
        rs0 += __shfl_xor_sync(0xffffffffu, rs0, 1);
        rs0 += __shfl_xor_sync(0xffffffffu, rs0, 2);
        rs1 += __shfl_xor_sync(0xffffffffu, rs1, 1);
        rs1 += __shfl_xor_sync(0xffffffffu, rs1, 2);
        l0 = l0 * al0 + rs0;
        l1 = l1 * al1 + rs1;

        __syncwarp();

        #pragma unroll
        for (int ks = 0; ks < AT_TK; ks += 8) {
            uint32_t a[4];
            a[0] = __float_as_uint(Ps[(mrow + qr    ) * PS_STRIDE + ks + qc    ]);
            a[1] = __float_as_uint(Ps[(mrow + qr + 8) * PS_STRIDE + ks + qc    ]);
            a[2] = __float_as_uint(Ps[(mrow + qr    ) * PS_STRIDE + ks + qc + 4]);
            a[3] = __float_as_uint(Ps[(mrow + qr + 8) * PS_STRIDE + ks + qc + 4]);
            #pragma unroll
            for (int nj = 0; nj < 8; nj++) {
                uint32_t bb[2];
                bb[0] = __float_as_uint(Vs[(ks + qc    ) * VS_STRIDE + nj * 8 + qr]);
                bb[1] = __float_as_uint(Vs[(ks + qc + 4) * VS_STRIDE + nj * 8 + qr]);
                mma_tf32(O[nj], a, bb);
            }
        }
        __syncthreads();
    }

    float inv0 = 1.f / l0, inv1 = 1.f / l1;
    int r0 = mrow + qr, r1 = mrow + qr + 8;
    #pragma unroll
    for (int nj = 0; nj < 8; nj++) {
        int c = h * HDIM + nj * 8 + 2 * qc;
        if (r0 < rows) {
            float* p = outbuf + (size_t)(qrow0 + r0) * D + c;
            p[0] = to_tf32(O[nj][0] * inv0);
            p[1] = to_tf32(O[nj][1] * inv0);
        }
        if (r1 < rows) {
            float* p = outbuf + (size_t)(qrow0 + r1) * D + c;
            p[0] = to_tf32(O[nj][2] * inv1);
            p[1] = to_tf32(O[nj][3] * inv1);
        }
    }
}

// ---------------------------------------------------------------------------
// Host: tensormap encoding via driver entry point (no -lcuda needed)
// ---------------------------------------------------------------------------
typedef CUresult (*EncodeFn)(CUtensorMap*, CUtensorMapDataType, cuuint32_t, void*,
                             const cuuint64_t*, const cuuint64_t*, const cuuint32_t*,
                             const cuuint32_t*, CUtensorMapInterleave, CUtensorMapSwizzle,
                             CUtensorMapL2promotion, CUtensorMapFloatOOBfill);

static EncodeFn get_encode_fn() {
    static EncodeFn fn = nullptr;
    if (!fn) {
        void* p = nullptr;
        cudaDriverEntryPointQueryResult st;
        cudaGetDriverEntryPointByVersion("cuTensorMapEncodeTiled", &p, 12000,
                                         cudaEnableDefault, &st);
        fn = (EncodeFn)p;
    }
    return fn;
}

static void make_tm(CUtensorMap* tm, void* ptr, uint64_t kdim, uint64_t rows,
                    uint32_t box_rows) {
    cuuint64_t dims[2]    = {kdim, rows};
    cuuint64_t strides[1] = {kdim * 4};
    cuuint32_t box[2]     = {32, box_rows};
    cuuint32_t es[2]      = {1, 1};
    get_encode_fn()(tm, CU_TENSOR_MAP_DATA_TYPE_FLOAT32, 2, ptr,
                    dims, strides, box, es,
                    CU_TENSOR_MAP_INTERLEAVE_NONE, CU_TENSOR_MAP_SWIZZLE_128B,
                    CU_TENSOR_MAP_L2_PROMOTION_L2_128B,
                    CU_TENSOR_MAP_FLOAT_OOB_FILL_NONE);
}

// ---------------------------------------------------------------------------
// kernel_launch
// ---------------------------------------------------------------------------
extern "C" void kernel_launch(void* const* d_in, const int* in_sizes, int n_in,
                              void* d_out, int out_size)
{
    const float* hidden = (const float*)d_in[0];
    const float* cross  = (const float*)d_in[1];
    const int*   seqs   = (const int*)d_in[2];
    const float* Wq  = (const float*)d_in[3];
    const float* bq  = (const float*)d_in[4];
    const float* Wkv = (const float*)d_in[5];
    const float* bkv = (const float*)d_in[6];
    const float* Wo  = (const float*)d_in[7];
    const float* bo  = (const float*)d_in[8];
    float* out = (float*)d_out;

    int qlen  = in_sizes[0] / D;
    int kvlen = in_sizes[1] / D;
    int nB    = in_sizes[2];
    int enc   = kvlen / nB;

    float *qbuf, *kvbuf, *abuf, *hidT, *crossT, *wqT, *wkvT, *woT;
    cudaGetSymbolAddress((void**)&qbuf, g_q);
    cudaGetSymbolAddress((void**)&kvbuf, g_kv);
    cudaGetSymbolAddress((void**)&abuf, g_attn);
    cudaGetSymbolAddress((void**)&hidT, g_hid);
    cudaGetSymbolAddress((void**)&crossT, g_cross);
    cudaGetSymbolAddress((void**)&wqT, g_wq);
    cudaGetSymbolAddress((void**)&wkvT, g_wkv);
    cudaGetSymbolAddress((void**)&woT, g_wo);

    cudaFuncSetAttribute(attn_mma_kernel,
                         cudaFuncAttributeMaxDynamicSharedMemorySize, ATTN_SMEM_BYTES);
    cudaFuncSetAttribute(tc_gemm_kernel,
                         cudaFuncAttributeMaxDynamicSharedMemorySize, GEMM_SMEM_BYTES);

    // Tensormaps (all sources are fixed-address scratch buffers)
    static CUtensorMap tmA_q, tmA_kv, tmA_o, tmB_q, tmB_kv, tmB_o;
    make_tm(&tmA_q,  hidT,   D, (uint64_t)qlen,  128);
    make_tm(&tmA_kv, crossT, D, (uint64_t)kvlen, 128);
    make_tm(&tmA_o,  abuf,   D, (uint64_t)qlen,  128);
    make_tm(&tmB_q,  wqT,  D, (uint64_t)D,     256);
    make_tm(&tmB_kv, wkvT, D, (uint64_t)(2*D), 256);
    make_tm(&tmB_o,  woT,  D, (uint64_t)D,     256);

    float scaling = 1.0f / sqrtf((float)HDIM);

    // ---- prep: round activations, transpose+round weights ----
    cvt_tf32_kernel<<<(in_sizes[0] / 4 + 255) / 256, 256>>>(hidden, hidT, in_sizes[0] / 4);
    cvt_tf32_kernel<<<(in_sizes[1] / 4 + 255) / 256, 256>>>(cross, crossT, in_sizes[1] / 4);
    transpose_cvt_kernel<<<dim3(D / 32, D / 32), dim3(32, 8)>>>(Wq, wqT, D, D);
    transpose_cvt_kernel<<<dim3(2 * D / 32, D / 32), dim3(32, 8)>>>(Wkv, wkvT, D, 2 * D);
    transpose_cvt_kernel<<<dim3(D / 32, D / 32), dim3(32, 8)>>>(Wo, woT, D, D);

    // ---- Q projection ----
    tc_gemm_kernel<<<dim3(D / BN, (qlen + BM - 1) / BM), 512, GEMM_SMEM_BYTES>>>(
        tmA_q, tmB_q, bq, qbuf, qlen, D, D, scaling, 1);

    // ---- KV projection ----
    tc_gemm_kernel<<<dim3(2 * D / BN, (kvlen + BM - 1) / BM), 512, GEMM_SMEM_BYTES>>>(
        tmA_kv, tmB_kv, bkv, kvbuf, kvlen, 2 * D, D, 1.0f, 1);

    // ---- attention ----
    int qtiles = (qlen + AT_TQ - 1) / AT_TQ;
    attn_mma_kernel<<<dim3(H, nB, qtiles), 256, ATTN_SMEM_BYTES>>>(
        qbuf, kvbuf, seqs, abuf, nB, enc);

    // ---- O projection ----
    tc_gemm_kernel<<<dim3(D / BN, (qlen + BM - 1) / BM), 512, GEMM_SMEM_BYTES>>>(
        tmA_o, tmB_o, bo, out, qlen, D, D, 1.0f, 0);
}

// round 10
// speedup vs baseline: 1.0005x; 1.0005x over previous
#include <cuda_runtime.h>
#include <cuda.h>
#include <math.h>
#include <stdint.h>

#define D    1280
#define H    20
#define HDIM 64

// Attention tiling (unchanged HMMA flash kernel)
#define AT_TQ 128
#define AT_TK 64
#define QS_STRIDE 68
#define KS_STRIDE 68
#define VS_STRIDE 72
#define PS_STRIDE 68
#define ATTN_SMEM_FLOATS (AT_TQ*QS_STRIDE + AT_TK*KS_STRIDE + AT_TK*VS_STRIDE + AT_TQ*PS_STRIDE)
#define ATTN_SMEM_BYTES (ATTN_SMEM_FLOATS * 4)

// GEMM tiling: 128M x 256N x 32K, 512 threads, 3-stage TMA pipeline
#define BM 128
#define BN 256
#define BK 32
#define STAGES 3
#define A_STAGE_BYTES 16384          // 128 x 32 floats
#define B_STAGE_BYTES 32768          // 256 x 32 floats
#define STAGE_BYTES   (A_STAGE_BYTES + B_STAGE_BYTES)   // 49152
#define SMEM_DATA0    1024
#define GEMM_SMEM_BYTES (SMEM_DATA0 + STAGES * STAGE_BYTES)   // 148480
#define TILE_TX STAGE_BYTES

// Scratch (allocation-free): fixed problem shapes.
__device__ float g_q[1600 * 1280];
__device__ float g_kv[6000 * 2560];
__device__ float g_attn[1600 * 1280];
__device__ float g_hid[1600 * 1280];
__device__ float g_cross[6000 * 1280];
__device__ float g_wq[1280 * 1280];    // transposed [N][K]
__device__ float g_wkv[2560 * 1280];   // transposed [N][K]
__device__ float g_wo[1280 * 1280];    // transposed [N][K]

// ---------------------------------------------------------------------------
// PTX helpers
// ---------------------------------------------------------------------------
__device__ __forceinline__ float to_tf32(float x) {
    uint32_t y;
    asm("cvt.rna.tf32.f32 %0, %1;" : "=r"(y) : "f"(x));
    return __uint_as_float(y);
}

__device__ __forceinline__ void mma_tf32(float* d, const uint32_t* a, const uint32_t* b) {
    asm volatile(
        "mma.sync.aligned.m16n8k8.row.col.f32.tf32.tf32.f32 "
        "{%0,%1,%2,%3}, {%4,%5,%6,%7}, {%8,%9}, {%0,%1,%2,%3};\n"
        : "+f"(d[0]), "+f"(d[1]), "+f"(d[2]), "+f"(d[3])
        : "r"(a[0]), "r"(a[1]), "r"(a[2]), "r"(a[3]), "r"(b[0]), "r"(b[1]));
}

__device__ __forceinline__ uint32_t smem_u32(const void* p) {
    return (uint32_t)__cvta_generic_to_shared(p);
}

#define MBARRIER_INIT(addr, count) \
    asm volatile("mbarrier.init.shared.b64 [%0], %1;" :: "r"((uint32_t)(addr)), "r"((uint32_t)(count)) : "memory")

#define MBARRIER_EXPECT_TX(addr, tx) \
    asm volatile("mbarrier.arrive.expect_tx.shared.b64 _, [%0], %1;" :: "r"((uint32_t)(addr)), "r"((uint32_t)(tx)) : "memory")

#define MBARRIER_WAIT_PARITY(mbar_smem_addr, phase_parity) do { \
    uint32_t _mbar = (uint32_t)(mbar_smem_addr); \
    uint32_t _parity = (uint32_t)(phase_parity); \
    uint32_t _done; \
    asm volatile( \
        "{\n\t.reg .pred p;\n\t" \
        "mbarrier.try_wait.parity.acquire.cta.shared::cta.b64 p, [%1], %2;\n\t" \
        "selp.b32 %0, 1, 0, p;\n\t}" \
        : "=r"(_done) : "r"(_mbar), "r"(_parity) : "memory"); \
    if (!_done) { \
        asm volatile( \
            "{\n\t.reg .pred P1;\n\t" \
            "WAIT_LOOP_%=:\n\t" \
            "mbarrier.try_wait.parity.acquire.cta.shared::cta.b64 P1, [%0], %1, 0x989680;\n\t" \
            "@P1 bra.uni WAIT_DONE_%=;\n\t" \
            "bra.uni WAIT_LOOP_%=;\n\t" \
            "WAIT_DONE_%=:\n\t}" \
            :: "r"(_mbar), "r"(_parity) : "memory"); \
    } \
} while(0)

#define TMA_LOAD_2D(smem_addr, map_ptr, cx, cy, mbar) \
    asm volatile( \
        "cp.async.bulk.tensor.2d.shared::cta.global.tile.mbarrier::complete_tx::bytes " \
        "[%0], [%1, {%2, %3}], [%4];" \
        :: "r"((uint32_t)(smem_addr)), "l"(map_ptr), "r"((int)(cx)), "r"((int)(cy)), \
           "r"((uint32_t)(mbar)) : "memory")

// ---------------------------------------------------------------------------
// Elementwise fp32 -> tf32(RN)
// ---------------------------------------------------------------------------
__global__ void cvt_tf32_kernel(const float* __restrict__ in,
                                float* __restrict__ out, int n4)
{
    int i = blockIdx.x * blockDim.x + threadIdx.x;
    if (i < n4) {
        float4 v = reinterpret_cast<const float4*>(in)[i];
        v.x = to_tf32(v.x); v.y = to_tf32(v.y);
        v.z = to_tf32(v.z); v.w = to_tf32(v.w);
        reinterpret_cast<float4*>(out)[i] = v;
    }
}

// ---------------------------------------------------------------------------
// Transpose + tf32 round: in[K][N] -> out[N][K]. K,N multiples of 32.
// ---------------------------------------------------------------------------
__global__ void transpose_cvt_kernel(const float* __restrict__ in,
                                     float* __restrict__ out, int K, int N)
{
    __shared__ float t[32][33];
    int k0 = blockIdx.y * 32, n0 = blockIdx.x * 32;
    int tx = threadIdx.x, ty = threadIdx.y;   // 32 x 8
    #pragma unroll
    for (int i = 0; i < 32; i += 8)
        t[ty + i][tx] = in[(size_t)(k0 + ty + i) * N + n0 + tx];
    __syncthreads();
    #pragma unroll
    for (int i = 0; i < 32; i += 8)
        out[(size_t)(n0 + ty + i) * K + k0 + tx] = to_tf32(t[tx][ty + i]);
}

// ---------------------------------------------------------------------------
// TMA + HMMA tf32 GEMM: C[M,N] = (A[M,K] @ Bt[N,K]^T + bias) * scale
// Tile 128x256x32, 512 threads = 16 warps (2M x 8N), warp tile 64x32.
// A/B staged via 2D TMA (SW128); fragment LDS uses the matching XOR swizzle.
// ---------------------------------------------------------------------------
__global__ __launch_bounds__(512, 1) void tc_gemm_kernel(
    const __grid_constant__ CUtensorMap tmA,
    const __grid_constant__ CUtensorMap tmB,
    const float* __restrict__ bias, float* __restrict__ C,
    int M, int N, int K, float scale, int round_out)
{
    extern __shared__ __align__(1024) char smem[];
    uint32_t sb = smem_u32(smem);

    int tid = threadIdx.x, wid = tid >> 5, lane = tid & 31;
    int wm = wid >> 3, wn = wid & 7;          // 2 x 8 warp grid
    int qr = lane >> 2, qc = lane & 3;
    int brow = blockIdx.y * BM;
    int bcol = blockIdx.x * BN;
    int ntiles = K / BK;
    int mBase = wm * 64, nBase = wn * 32;

    if (tid < STAGES) MBARRIER_INIT(sb + tid * 8, 1);
    __syncthreads();

    // Prefetch stages 0..STAGES-2
    if (tid == 0) {
        #pragma unroll
        for (int s = 0; s < STAGES - 1; s++) {
            MBARRIER_EXPECT_TX(sb + s * 8, TILE_TX);
            TMA_LOAD_2D(sb + SMEM_DATA0 + s * STAGE_BYTES, &tmA, s * BK, brow, sb + s * 8);
            TMA_LOAD_2D(sb + SMEM_DATA0 + s * STAGE_BYTES + A_STAGE_BYTES, &tmB,
                        s * BK, bcol, sb + s * 8);
        }
    }

    float acc[4][4][4];
    #pragma unroll
    for (int i = 0; i < 4; i++)
        #pragma unroll
        for (int j = 0; j < 4; j++)
            #pragma unroll
            for (int t = 0; t < 4; t++) acc[i][j][t] = 0.f;

    // Swizzled row byte offsets (TMA SW128: chunk ^= (row & 7), xor term = qr<<4)
    uint32_t xorv = (uint32_t)(qr << 4);
    uint32_t aOff[4], bOff[4];
    #pragma unroll
    for (int mi = 0; mi < 4; mi++) aOff[mi] = (uint32_t)(mBase + mi * 16 + qr) * 128u;
    #pragma unroll
    for (int nj = 0; nj < 4; nj++) bOff[nj] = (uint32_t)(nBase + nj * 8 + qr) * 128u;

    int ph[STAGES] = {0, 0, 0};

    for (int t = 0; t < ntiles; t++) {
        int buf = t % STAGES;
        // Issue stage t+STAGES-1 (its buffer was last consumed at t-1; synced below)
        if (t + STAGES - 1 < ntiles && tid == 0) {
            int nb = (t + STAGES - 1) % STAGES;
            MBARRIER_EXPECT_TX(sb + nb * 8, TILE_TX);
            TMA_LOAD_2D(sb + SMEM_DATA0 + nb * STAGE_BYTES, &tmA,
                        (t + STAGES - 1) * BK, brow, sb + nb * 8);
            TMA_LOAD_2D(sb + SMEM_DATA0 + nb * STAGE_BYTES + A_STAGE_BYTES, &tmB,
                        (t + STAGES - 1) * BK, bcol, sb + nb * 8);
        }

        MBARRIER_WAIT_PARITY(sb + buf * 8, ph[buf]);
        ph[buf] ^= 1;

        const char* Ab = smem + SMEM_DATA0 + buf * STAGE_BYTES;
        const char* Bb = Ab + A_STAGE_BYTES;

        #pragma unroll
        for (int ks = 0; ks < 32; ks += 8) {
            uint32_t c0 = ((uint32_t)((ks + qc) * 4)) ^ xorv;
            uint32_t c1 = ((uint32_t)((ks + qc + 4) * 4)) ^ xorv;
            uint32_t af[4][4], bf[4][2];
            #pragma unroll
            for (int mi = 0; mi < 4; mi++) {
                af[mi][0] = *(const uint32_t*)(Ab + aOff[mi] + c0);
                af[mi][1] = *(const uint32_t*)(Ab + aOff[mi] + 1024 + c0);
                af[mi][2] = *(const uint32_t*)(Ab + aOff[mi] + c1);
                af[mi][3] = *(const uint32_t*)(Ab + aOff[mi] + 1024 + c1);
            }
            #pragma unroll
            for (int nj = 0; nj < 4; nj++) {
                bf[nj][0] = *(const uint32_t*)(Bb + bOff[nj] + c0);
                bf[nj][1] = *(const uint32_t*)(Bb + bOff[nj] + c1);
            }
            #pragma unroll
            for (int mi = 0; mi < 4; mi++)
                #pragma unroll
                for (int nj = 0; nj < 4; nj++)
                    mma_tf32(acc[mi][nj], af[mi], bf[nj]);
        }
        __syncthreads();
    }

    // ---- epilogue ----
    #pragma unroll
    for (int mi = 0; mi < 4; mi++) {
        int row0 = brow + mBase + mi * 16 + qr;
        #pragma unroll
        for (int nj = 0; nj < 4; nj++) {
            int col0 = bcol + nBase + nj * 8 + qc * 2;
            float b0 = bias[col0], b1 = bias[col0 + 1];
            float v00 = (acc[mi][nj][0] + b0) * scale;
            float v01 = (acc[mi][nj][1] + b1) * scale;
            float v10 = (acc[mi][nj][2] + b0) * scale;
            float v11 = (acc[mi][nj][3] + b1) * scale;
            if (round_out) {
                v00 = to_tf32(v00); v01 = to_tf32(v01);
                v10 = to_tf32(v10); v11 = to_tf32(v11);
            }
            if (row0 < M) {
                C[(size_t)row0 * N + col0    ] = v00;
                C[(size_t)row0 * N + col0 + 1] = v01;
            }
            if (row0 + 8 < M) {
                C[(size_t)(row0 + 8) * N + col0    ] = v10;
                C[(size_t)(row0 + 8) * N + col0 + 1] = v11;
            }
        }
    }
}

// ---------------------------------------------------------------------------
// Tensor-core flash attention (HMMA tf32, unchanged). Inputs pre-rounded.
// ---------------------------------------------------------------------------
__global__ __launch_bounds__(256) void attn_mma_kernel(
    const float* __restrict__ q, const float* __restrict__ kv,
    const int* __restrict__ seq_lens, float* __restrict__ outbuf,
    int nB, int enc)
{
    extern __shared__ float sm[];
    float* Qs = sm;
    float* Ks = Qs + AT_TQ * QS_STRIDE;
    float* Vs = Ks + AT_TK * KS_STRIDE;
    float* Ps = Vs + AT_TK * VS_STRIDE;

    int h = blockIdx.x, b = blockIdx.y, tile = blockIdx.z;
    int qstart = 0;
    for (int i = 0; i < b; i++) qstart += seq_lens[i];
    int qlen = seq_lens[b];
    if (tile * AT_TQ >= qlen) return;
    int qrow0 = qstart + tile * AT_TQ;
    int rows = min(AT_TQ, qlen - tile * AT_TQ);
    size_t kvbase = (size_t)b * enc;

    int tid = threadIdx.x, wid = tid >> 5, lane = tid & 31;
    int qr = lane >> 2, qc = lane & 3;
    int mrow = wid * 16;

    for (int i = tid; i < AT_TQ * 16; i += 256) {
        int r = i >> 4, c4 = (i & 15) << 2;
        float4 v = make_float4(0.f, 0.f, 0.f, 0.f);
        if (r < rows)
            v = *reinterpret_cast<const float4*>(q + (size_t)(qrow0 + r) * D + h * HDIM + c4);
        *reinterpret_cast<float4*>(Qs + r * QS_STRIDE + c4) = v;
    }

    float O[8][4];
    #pragma unroll
    for (int nj = 0; nj < 8; nj++)
        #pragma unroll
        for (int t = 0; t < 4; t++) O[nj][t] = 0.f;
    float m0 = -1e30f, m1 = -1e30f, l0 = 0.f, l1 = 0.f;

    __syncthreads();

    for (int kc = 0; kc < enc; kc += AT_TK) {
        int kn = min(AT_TK, enc - kc);

        for (int i = tid; i < AT_TK * 16; i += 256) {
            int r = i >> 4, c4 = (i & 15) << 2;
            float4 kv4 = make_float4(0.f, 0.f, 0.f, 0.f);
            float4 vv4 = make_float4(0.f, 0.f, 0.f, 0.f);
            if (r < kn) {
                const float* rp = kv + (kvbase + kc + r) * (size_t)(2 * D) + h * HDIM;
                kv4 = *reinterpret_cast<const float4*>(rp + c4);
                vv4 = *reinterpret_cast<const float4*>(rp + D + c4);
            }
            *reinterpret_cast<float4*>(Ks + r * KS_STRIDE + c4) = kv4;
            *reinterpret_cast<float4*>(Vs + r * VS_STRIDE + c4) = vv4;
        }
        __syncthreads();

        float s[8][4];
        #pragma unroll
        for (int nj = 0; nj < 8; nj++)
            #pragma unroll
            for (int t = 0; t < 4; t++) s[nj][t] = 0.f;

        #pragma unroll
        for (int ks = 0; ks < AT_TK; ks += 8) {
            uint32_t a[4];
            a[0] = __float_as_uint(Qs[(mrow + qr    ) * QS_STRIDE + ks + qc    ]);
            a[1] = __float_as_uint(Qs[(mrow + qr + 8) * QS_STRIDE + ks + qc    ]);
            a[2] = __float_as_uint(Qs[(mrow + qr    ) * QS_STRIDE + ks + qc + 4]);
            a[3] = __float_as_uint(Qs[(mrow + qr + 8) * QS_STRIDE + ks + qc + 4]);
            #pragma unroll
            for (int nj = 0; nj < 8; nj++) {
                uint32_t bb[2];
                bb[0] = __float_as_uint(Ks[(nj * 8 + qr) * KS_STRIDE + ks + qc    ]);
                bb[1] = __float_as_uint(Ks[(nj * 8 + qr) * KS_STRIDE + ks + qc + 4]);
                mma_tf32(s[nj], a, bb);
            }
        }

        if (kn < AT_TK) {
            #pragma unroll
            for (int nj = 0; nj < 8; nj++) {
                int c0 = nj * 8 + 2 * qc;
                if (c0     >= kn) { s[nj][0] = -1e30f; s[nj][2] = -1e30f; }
                if (c0 + 1 >= kn) { s[nj][1] = -1e30f; s[nj][3] = -1e30f; }
            }
        }

        float mx0 = -1e30f, mx1 = -1e30f;
        #pragma unroll
        for (int nj = 0; nj < 8; nj++) {
            mx0 = fmaxf(mx0, fmaxf(s[nj][0], s[nj][1]));
            mx1 = fmaxf(mx1, fmaxf(s[nj][2], s[nj][3]));
        }
        mx0 = fmaxf(mx0, __shfl_xor_sync(0xffffffffu, mx0, 1));
        mx0 = fmaxf(mx0, __shfl_xor_sync(0xffffffffu, mx0, 2));
        mx1 = fmaxf(mx1, __shfl_xor_sync(0xffffffffu, mx1, 1));
        mx1 = fmaxf(mx1, __shfl_xor_sync(0xffffffffu, mx1, 2));

        float mn0 = fmaxf(m0, mx0), mn1 = fmaxf(m1, mx1);
        float al0 = __expf(m0 - mn0), al1 = __expf(m1 - mn1);
        m0 = mn0; m1 = mn1;

        float rs0 = 0.f, rs1 = 0.f;
        #pragma unroll
        for (int nj = 0; nj < 8; nj++) {
            float p0 = __expf(s[nj][0] - mn0);
            float p1 = __expf(s[nj][1] - mn0);
            float p2 = __expf(s[nj][2] - mn1);
            float p3 = __expf(s[nj][3] - mn1);
            rs0 += p0 + p1; rs1 += p2 + p3;
            int c = nj * 8 + 2 * qc;
            Ps[(mrow + qr    ) * PS_STRIDE + c    ] = to_tf32(p0);
            Ps[(mrow + qr    ) * PS_STRIDE + c + 1] = to_tf32(p1);
            Ps[(mrow + qr + 8) * PS_STRIDE + c    ] = to_tf32(p2);
            Ps[(mrow + qr + 8) * PS_STRIDE + c + 1] = to_tf32(p3);
            O[nj][0] *= al0; O[nj][1] *= al0;
            O[nj][2] *= al1; O[nj][3] *= al1;
        }
        rs0 += __shfl_xor_sync(0xffffffffu, rs0, 1);
        rs0 += __shfl_xor_sync(0xffffffffu, rs0, 2);
        rs1 += __shfl_xor_sync(0xffffffffu, rs1, 1);
        rs1 += __shfl_xor_sync(0xffffffffu, rs1, 2);
        l0 = l0 * al0 + rs0;
        l1 = l1 * al1 + rs1;

        __syncwarp();

        #pragma unroll
        for (int ks = 0; ks < AT_TK; ks += 8) {
            uint32_t a[4];
            a[0] = __float_as_uint(Ps[(mrow + qr    ) * PS_STRIDE + ks + qc    ]);
            a[1] = __float_as_uint(Ps[(mrow + qr + 8) * PS_STRIDE + ks + qc    ]);
            a[2] = __float_as_uint(Ps[(mrow + qr    ) * PS_STRIDE + ks + qc + 4]);
            a[3] = __float_as_uint(Ps[(mrow + qr + 8) * PS_STRIDE + ks + qc + 4]);
            #pragma unroll
            for (int nj = 0; nj < 8; nj++) {
                uint32_t bb[2];
                bb[0] = __float_as_uint(Vs[(ks + qc    ) * VS_STRIDE + nj * 8 + qr]);
                bb[1] = __float_as_uint(Vs[(ks + qc + 4) * VS_STRIDE + nj * 8 + qr]);
                mma_tf32(O[nj], a, bb);
            }
        }
        __syncthreads();
    }

    float inv0 = 1.f / l0, inv1 = 1.f / l1;
    int r0 = mrow + qr, r1 = mrow + qr + 8;
    #pragma unroll
    for (int nj = 0; nj < 8; nj++) {
        int c = h * HDIM + nj * 8 + 2 * qc;
        if (r0 < rows) {
            float* p = outbuf + (size_t)(qrow0 + r0) * D + c;
            p[0] = to_tf32(O[nj][0] * inv0);
            p[1] = to_tf32(O[nj][1] * inv0);
        }
        if (r1 < rows) {
            float* p = outbuf + (size_t)(qrow0 + r1) * D + c;
            p[0] = to_tf32(O[nj][2] * inv1);
            p[1] = to_tf32(O[nj][3] * inv1);
        }
    }
}

// ---------------------------------------------------------------------------
// Host: tensormap encoding via driver entry point (no -lcuda needed)
// ---------------------------------------------------------------------------
typedef CUresult (*EncodeFn)(CUtensorMap*, CUtensorMapDataType, cuuint32_t, void*,
                             const cuuint64_t*, const cuuint64_t*, const cuuint32_t*,
                             const cuuint32_t*, CUtensorMapInterleave, CUtensorMapSwizzle,
                             CUtensorMapL2promotion, CUtensorMapFloatOOBfill);

static EncodeFn get_encode_fn() {
    static EncodeFn fn = nullptr;
    if (!fn) {
        void* p = nullptr;
        cudaDriverEntryPointQueryResult st;
        cudaGetDriverEntryPointByVersion("cuTensorMapEncodeTiled", &p, 12000,
                                         cudaEnableDefault, &st);
        fn = (EncodeFn)p;
    }
    return fn;
}

static void make_tm(CUtensorMap* tm, void* ptr, uint64_t kdim, uint64_t rows,
                    uint32_t box_rows) {
    cuuint64_t dims[2]    = {kdim, rows};
    cuuint64_t strides[1] = {kdim * 4};
    cuuint32_t box[2]     = {32, box_rows};
    cuuint32_t es[2]      = {1, 1};
    get_encode_fn()(tm, CU_TENSOR_MAP_DATA_TYPE_FLOAT32, 2, ptr,
                    dims, strides, box, es,
                    CU_TENSOR_MAP_INTERLEAVE_NONE, CU_TENSOR_MAP_SWIZZLE_128B,
                    CU_TENSOR_MAP_L2_PROMOTION_L2_128B,
                    CU_TENSOR_MAP_FLOAT_OOB_FILL_NONE);
}

// ---------------------------------------------------------------------------
// kernel_launch
// ---------------------------------------------------------------------------
extern "C" void kernel_launch(void* const* d_in, const int* in_sizes, int n_in,
                              void* d_out, int out_size)
{
    const float* hidden = (const float*)d_in[0];
    const float* cross  = (const float*)d_in[1];
    const int*   seqs   = (const int*)d_in[2];
    const float* Wq  = (const float*)d_in[3];
    const float* bq  = (const float*)d_in[4];
    const float* Wkv = (const float*)d_in[5];
    const float* bkv = (const float*)d_in[6];
    const float* Wo  = (const float*)d_in[7];
    const float* bo  = (const float*)d_in[8];
    float* out = (float*)d_out;

    int qlen  = in_sizes[0] / D;
    int kvlen = in_sizes[1] / D;
    int nB    = in_sizes[2];
    int enc   = kvlen / nB;

    float *qbuf, *kvbuf, *abuf, *hidT, *crossT, *wqT, *wkvT, *woT;
    cudaGetSymbolAddress((void**)&qbuf, g_q);
    cudaGetSymbolAddress((void**)&kvbuf, g_kv);
    cudaGetSymbolAddress((void**)&abuf, g_attn);
    cudaGetSymbolAddress((void**)&hidT, g_hid);
    cudaGetSymbolAddress((void**)&crossT, g_cross);
    cudaGetSymbolAddress((void**)&wqT, g_wq);
    cudaGetSymbolAddress((void**)&wkvT, g_wkv);
    cudaGetSymbolAddress((void**)&woT, g_wo);

    cudaFuncSetAttribute(attn_mma_kernel,
                         cudaFuncAttributeMaxDynamicSharedMemorySize, ATTN_SMEM_BYTES);
    cudaFuncSetAttribute(tc_gemm_kernel,
                         cudaFuncAttributeMaxDynamicSharedMemorySize, GEMM_SMEM_BYTES);

    // Tensormaps (all sources are fixed-address scratch buffers)
    static CUtensorMap tmA_q, tmA_kv, tmA_o, tmB_q, tmB_kv, tmB_o;
    make_tm(&tmA_q,  hidT,   D, (uint64_t)qlen,  128);
    make_tm(&tmA_kv, crossT, D, (uint64_t)kvlen, 128);
    make_tm(&tmA_o,  abuf,   D, (uint64_t)qlen,  128);
    make_tm(&tmB_q,  wqT,  D, (uint64_t)D,     256);
    make_tm(&tmB_kv, wkvT, D, (uint64_t)(2*D), 256);
    make_tm(&tmB_o,  woT,  D, (uint64_t)D,     256);

    float scaling = 1.0f / sqrtf((float)HDIM);

    // ---- prep: round activations, transpose+round weights ----
    cvt_tf32_kernel<<<(in_sizes[0] / 4 + 255) / 256, 256>>>(hidden, hidT, in_sizes[0] / 4);
    cvt_tf32_kernel<<<(in_sizes[1] / 4 + 255) / 256, 256>>>(cross, crossT, in_sizes[1] / 4);
    transpose_cvt_kernel<<<dim3(D / 32, D / 32), dim3(32, 8)>>>(Wq, wqT, D, D);
    transpose_cvt_kernel<<<dim3(2 * D / 32, D / 32), dim3(32, 8)>>>(Wkv, wkvT, D, 2 * D);
    transpose_cvt_kernel<<<dim3(D / 32, D / 32), dim3(32, 8)>>>(Wo, woT, D, D);

    // ---- Q projection ----
    tc_gemm_kernel<<<dim3(D / BN, (qlen + BM - 1) / BM), 512, GEMM_SMEM_BYTES>>>(
        tmA_q, tmB_q, bq, qbuf, qlen, D, D, scaling, 1);

    // ---- KV projection ----
    tc_gemm_kernel<<<dim3(2 * D / BN, (kvlen + BM - 1) / BM), 512, GEMM_SMEM_BYTES>>>(
        tmA_kv, tmB_kv, bkv, kvbuf, kvlen, 2 * D, D, 1.0f, 1);

    // ---- attention ----
    int qtiles = (qlen + AT_TQ - 1) / AT_TQ;
    attn_mma_kernel<<<dim3(H, nB, qtiles), 256, ATTN_SMEM_BYTES>>>(
        qbuf, kvbuf, seqs, abuf, nB, enc);

    // ---- O projection ----
    tc_gemm_kernel<<<dim3(D / BN, (qlen + BM - 1) / BM), 512, GEMM_SMEM_BYTES>>>(
        tmA_o, tmB_o, bo, out, qlen, D, D, 1.0f, 0);
}